// round 1
// baseline (speedup 1.0000x reference)
#include <cuda_runtime.h>
#include <math.h>

#define BZ 4
#define LZ 2048
#define WD 2048
#define NHD 32
#define HDM 64
#define MBSZ 16
#define NMBC 128
#define EPSC 1e-6f
#define ELEMS (BZ*LZ*WD)

// ---------------- scratch (device globals; no allocation) ----------------
__device__ float g_xq[ELEMS];    // q-projection; later reused as post-norm output
__device__ float g_xv[ELEMS];    // v-projection
__device__ float g_XQ[ELEMS];    // conv+rope Q
__device__ float g_XK[ELEMS];    // conv+rope K
__device__ float g_scan[ELEMS];  // scan output (pre post-norm)
__device__ float g_lr[BZ*NHD*NMBC*MBSZ];

__device__ __forceinline__ float* sel_ptr(int sel) {
    switch (sel) {
        case 1: return g_xq;
        case 2: return g_xv;
        case 5: return g_scan;
    }
    return nullptr;
}

// ---------------- SGEMM: C[m,n] = sum_k A[m,k]*B[n,k] ----------------
// 128x128 tile, K-tile 16, 256 threads, 8x8 per-thread microtile.
__global__ __launch_bounds__(256) void ttt_sgemm_nt(
    const float* __restrict__ Aext, int asel,
    const float* __restrict__ Bm,
    float* Cext, int csel,
    int M, int N, int K)
{
    const float* A = asel ? (const float*)sel_ptr(asel) : Aext;
    float* C = csel ? sel_ptr(csel) : Cext;

    __shared__ float As[16][132];
    __shared__ float Bs[16][132];

    int tid = threadIdx.x;
    int tx = tid & 15;        // n group
    int ty = tid >> 4;        // m group
    int m0 = blockIdx.y * 128;
    int n0 = blockIdx.x * 128;

    float acc[8][8];
#pragma unroll
    for (int i = 0; i < 8; i++)
#pragma unroll
        for (int j = 0; j < 8; j++) acc[i][j] = 0.0f;

    for (int kt = 0; kt < K; kt += 16) {
#pragma unroll
        for (int p = 0; p < 2; p++) {
            int idx = tid + p * 256;          // [0,512)
            int r  = idx >> 2;                // row within tile
            int kq = (idx & 3) * 4;           // k offset
            float4 va = *reinterpret_cast<const float4*>(&A[(size_t)(m0 + r) * K + kt + kq]);
            As[kq + 0][r] = va.x; As[kq + 1][r] = va.y; As[kq + 2][r] = va.z; As[kq + 3][r] = va.w;
            float4 vb = *reinterpret_cast<const float4*>(&Bm[(size_t)(n0 + r) * K + kt + kq]);
            Bs[kq + 0][r] = vb.x; Bs[kq + 1][r] = vb.y; Bs[kq + 2][r] = vb.z; Bs[kq + 3][r] = vb.w;
        }
        __syncthreads();

#pragma unroll
        for (int k = 0; k < 16; k++) {
            float a[8], b[8];
            *(float4*)&a[0] = *(const float4*)&As[k][ty * 4];
            *(float4*)&a[4] = *(const float4*)&As[k][64 + ty * 4];
            *(float4*)&b[0] = *(const float4*)&Bs[k][tx * 4];
            *(float4*)&b[4] = *(const float4*)&Bs[k][64 + tx * 4];
#pragma unroll
            for (int i = 0; i < 8; i++)
#pragma unroll
                for (int j = 0; j < 8; j++)
                    acc[i][j] += a[i] * b[j];
        }
        __syncthreads();
    }

#pragma unroll
    for (int ih = 0; ih < 2; ih++) {
#pragma unroll
        for (int iv = 0; iv < 4; iv++) {
            int m = m0 + ih * 64 + ty * 4 + iv;
            float* crow = C + (size_t)m * N + n0;
            int ai = ih * 4 + iv;
            float4 c0 = make_float4(acc[ai][0], acc[ai][1], acc[ai][2], acc[ai][3]);
            float4 c1 = make_float4(acc[ai][4], acc[ai][5], acc[ai][6], acc[ai][7]);
            *(float4*)&crow[tx * 4] = c0;
            *(float4*)&crow[64 + tx * 4] = c1;
        }
    }
}

// ---------------- causal dwconv (q and k) + interleaved RoPE ----------------
// one thread per channel PAIR; reads g_xq, writes g_XQ/g_XK (b,l,width layout)
__global__ __launch_bounds__(256) void ttt_conv_rope(
    const float* __restrict__ cqw, const float* __restrict__ cqb,
    const float* __restrict__ ckw, const float* __restrict__ ckb)
{
    int idx = blockIdx.x * 256 + threadIdx.x;   // pair index < BZ*LZ*WD/2
    int pr = idx & (WD / 2 - 1);                // pair within row
    int bl = idx >> 10;                         // b*LZ + l
    int l  = bl & (LZ - 1);
    int ch = pr * 2;

    float q0 = cqb[ch], q1 = cqb[ch + 1];
    float k0 = ckb[ch], k1 = ckb[ch + 1];
    const float2* xin = (const float2*)g_xq;
#pragma unroll
    for (int k = 0; k < 4; k++) {
        int ls = l - 3 + k;
        if (ls >= 0) {
            float2 v = xin[(size_t)(bl - 3 + k) * (WD / 2) + pr];
            q0 += v.x * cqw[ch * 4 + k];       q1 += v.y * cqw[(ch + 1) * 4 + k];
            k0 += v.x * ckw[ch * 4 + k];       k1 += v.y * ckw[(ch + 1) * 4 + k];
        }
    }
    int i = (ch & 63) >> 1;                            // pair index within head
    float fr = (float)(l & 15) * powf(10000.0f, -(float)i * (1.0f / 32.0f));
    float sn, cs;
    sincosf(fr, &sn, &cs);
    float2 oq = make_float2(q0 * cs - q1 * sn, q1 * cs + q0 * sn);
    float2 ok = make_float2(k0 * cs - k1 * sn, k1 * cs + k0 * sn);
    ((float2*)g_XQ)[idx] = oq;
    ((float2*)g_XK)[idx] = ok;
}

// ---------------- ttt_lr: sigmoid(hs . lr_w[h] + lr_b[h]) / HD ----------------
__global__ __launch_bounds__(256) void ttt_lr_kernel(
    const float* __restrict__ hs, const float* __restrict__ w,
    const float* __restrict__ bias)
{
    __shared__ float row[WD];
    int bl = blockIdx.x, tid = threadIdx.x;
    const float4* src = (const float4*)(hs + (size_t)bl * WD);
    ((float4*)row)[tid]       = src[tid];
    ((float4*)row)[tid + 256] = src[tid + 256];
    __syncthreads();
    int warp = tid >> 5, lane = tid & 31;
    int b = bl >> 11, l = bl & (LZ - 1);
#pragma unroll
    for (int hh = 0; hh < 4; hh++) {
        int h = warp * 4 + hh;
        const float4* wr = (const float4*)(w + (size_t)h * WD);
        const float4* rr = (const float4*)row;
        float s = 0.0f;
#pragma unroll 4
        for (int c = lane; c < WD / 4; c += 32) {
            float4 a = rr[c], bb = wr[c];
            s += a.x * bb.x + a.y * bb.y + a.z * bb.z + a.w * bb.w;
        }
#pragma unroll
        for (int o = 16; o; o >>= 1) s += __shfl_xor_sync(0xffffffffu, s, o);
        if (lane == 0) {
            float sg = 1.0f / (1.0f + expf(-(s + bias[h])));
            g_lr[(((size_t)b * NHD + h) * NMBC + (l >> 4)) * MBSZ + (l & 15)] = sg * (1.0f / 64.0f);
        }
    }
}

// ---------------- the TTT scan: one block per (b,h) ----------------
__global__ __launch_bounds__(256) void ttt_scan_kernel(
    const float* __restrict__ lt_idx,
    const float* __restrict__ lnw_g, const float* __restrict__ lnb_g,
    const float* __restrict__ W1g,   const float* __restrict__ b1g)
{
    __shared__ float W1[64][64];
    __shared__ float sxq[16][68], sxk[16][68], sxv[16][68];
    __shared__ float grad[16][68], z[16][68];
    __shared__ float attn[16][16];
    __shared__ float b1[64], lnw[64], lnb[64], lr[16], tok[16];

    int tid = threadIdx.x;
    int b = blockIdx.x >> 5, h = blockIdx.x & 31;

    for (int o = tid; o < 4096; o += 256)
        ((float*)W1)[o] = W1g[(size_t)h * 4096 + o];
    if (tid < 64) {
        b1[tid]  = b1g[h * 64 + tid];
        lnw[tid] = lnw_g[h * 64 + tid];
        lnb[tid] = lnb_g[h * 64 + tid];
    }
    if (tid < 16) tok[tid] = fmaxf(1.0f / (float)(tid + 1) + lt_idx[tid], 0.0f);
    __syncthreads();

    const int warp = tid >> 5, lane = tid & 31;
    const int ii = tid >> 4;          // row 0..15
    const int d0 = (tid & 15) * 4;    // column base
    const size_t base = ((size_t)b * LZ) * WD + (size_t)h * HDM;

    for (int n = 0; n < NMBC; n++) {
        // load tiles
        {
            size_t g0 = base + (size_t)(n * MBSZ + ii) * WD + d0;
            *(float4*)&sxq[ii][d0] = *(const float4*)&g_XQ[g0];
            *(float4*)&sxk[ii][d0] = *(const float4*)&g_XK[g0];
            *(float4*)&sxv[ii][d0] = *(const float4*)&g_xv[g0];
        }
        if (tid < 16) lr[tid] = g_lr[(((size_t)b * NHD + h) * NMBC + n) * MBSZ + tid];
        __syncthreads();

        // Z1 = xk @ W1 + b1
        {
            float4 acc = *(const float4*)&b1[d0];
#pragma unroll 8
            for (int e = 0; e < 64; e++) {
                float xe = sxk[ii][e];
                float4 w = *(const float4*)&W1[e][d0];
                acc.x += xe * w.x; acc.y += xe * w.y; acc.z += xe * w.z; acc.w += xe * w.w;
            }
            *(float4*)&z[ii][d0] = acc;
        }
        // Attn = xq @ xk^T (16x16, one output per thread)
        {
            int i = tid >> 4, j = tid & 15;
            float s = 0.0f;
#pragma unroll 8
            for (int d = 0; d < 64; d++) s += sxq[i][d] * sxk[j][d];
            attn[i][j] = s;
        }
        __syncthreads();

        // grad = ln_l2_bwd(Z1, xv-xk) — warp w handles rows 2w, 2w+1
        {
#pragma unroll
            for (int rr = 0; rr < 2; rr++) {
                int r = warp * 2 + rr;
                float x0 = z[r][lane], x1 = z[r][lane + 32];
                float s = x0 + x1;
#pragma unroll
                for (int o = 16; o; o >>= 1) s += __shfl_xor_sync(0xffffffffu, s, o);
                float mu = s * (1.0f / 64.0f);
                float e0 = x0 - mu, e1 = x1 - mu;
                float v = e0 * e0 + e1 * e1;
#pragma unroll
                for (int o = 16; o; o >>= 1) v += __shfl_xor_sync(0xffffffffu, v, o);
                float rstd = rsqrtf(v * (1.0f / 64.0f) + EPSC);
                float xh0 = e0 * rstd, xh1 = e1 * rstd;
                float t0 = sxv[r][lane] - sxk[r][lane];
                float t1 = sxv[r][lane + 32] - sxk[r][lane + 32];
                float gy0 = (lnw[lane] * xh0 + lnb[lane] - t0) * lnw[lane];
                float gy1 = (lnw[lane + 32] * xh1 + lnb[lane + 32] - t1) * lnw[lane + 32];
                float s1 = gy0 + gy1, s2 = gy0 * xh0 + gy1 * xh1;
#pragma unroll
                for (int o = 16; o; o >>= 1) {
                    s1 += __shfl_xor_sync(0xffffffffu, s1, o);
                    s2 += __shfl_xor_sync(0xffffffffu, s2, o);
                }
                float sc = rstd * (1.0f / 64.0f);
                grad[r][lane]      = (64.0f * gy0 - s1 - xh0 * s2) * sc;
                grad[r][lane + 32] = (64.0f * gy1 - s1 - xh1 * s2) * sc;
            }
        }
        __syncthreads();

        // Z1_bar[i,d] = xq@W1 + b1 - tok[i]*sum_{j<=i} lr[j]*(Attn[i,j]+1)*grad[j,d]
        {
            float4 acc = *(const float4*)&b1[d0];
#pragma unroll 8
            for (int e = 0; e < 64; e++) {
                float xe = sxq[ii][e];
                float4 w = *(const float4*)&W1[e][d0];
                acc.x += xe * w.x; acc.y += xe * w.y; acc.z += xe * w.z; acc.w += xe * w.w;
            }
            float tk = tok[ii];
            for (int j = 0; j <= ii; j++) {
                float cf = tk * lr[j] * (attn[ii][j] + 1.0f);
                float4 gr = *(const float4*)&grad[j][d0];
                acc.x -= cf * gr.x; acc.y -= cf * gr.y; acc.z -= cf * gr.z; acc.w -= cf * gr.w;
            }
            *(float4*)&z[ii][d0] = acc;
        }
        __syncthreads();

        // out = xq + ln_fwd(Z1_bar)
        {
#pragma unroll
            for (int rr = 0; rr < 2; rr++) {
                int r = warp * 2 + rr;
                float x0 = z[r][lane], x1 = z[r][lane + 32];
                float s = x0 + x1;
#pragma unroll
                for (int o = 16; o; o >>= 1) s += __shfl_xor_sync(0xffffffffu, s, o);
                float mu = s * (1.0f / 64.0f);
                float e0 = x0 - mu, e1 = x1 - mu;
                float v = e0 * e0 + e1 * e1;
#pragma unroll
                for (int o = 16; o; o >>= 1) v += __shfl_xor_sync(0xffffffffu, v, o);
                float rstd = rsqrtf(v * (1.0f / 64.0f) + EPSC);
                size_t go = base + (size_t)(n * MBSZ + r) * WD;
                g_scan[go + lane]      = sxq[r][lane]      + lnw[lane] * (e0 * rstd)      + lnb[lane];
                g_scan[go + lane + 32] = sxq[r][lane + 32] + lnw[lane + 32] * (e1 * rstd) + lnb[lane + 32];
            }
        }

        // W1 -= tok[15] * (lr*xk)^T @ grad ; b1 -= tok[15] * sum_j lr[j]*grad[j,:]
        {
            float te = tok[15];
#pragma unroll
            for (int p = 0; p < 4; p++) {
                int d = ii * 4 + p;
                float4 acc = *(const float4*)&W1[d][d0];
#pragma unroll
                for (int j = 0; j < 16; j++) {
                    float cf = te * lr[j] * sxk[j][d];
                    float4 gr = *(const float4*)&grad[j][d0];
                    acc.x -= cf * gr.x; acc.y -= cf * gr.y; acc.z -= cf * gr.z; acc.w -= cf * gr.w;
                }
                *(float4*)&W1[d][d0] = acc;
            }
            if (tid < 64) {
                float s = 0.0f;
#pragma unroll
                for (int j = 0; j < 16; j++) s += lr[j] * grad[j][tid];
                b1[tid] -= te * s;
            }
        }
        __syncthreads();
    }
}

// ---------------- post layer-norm (width=2048) ----------------
__global__ __launch_bounds__(256) void ttt_postnorm(
    const float* __restrict__ pw, const float* __restrict__ pb)
{
    __shared__ float red[8];
    int bl = blockIdx.x, tid = threadIdx.x;
    int lane = tid & 31, warp = tid >> 5;
    const float4* src = (const float4*)(g_scan + (size_t)bl * WD);
    float4 v0 = src[tid], v1 = src[tid + 256];

    float s = v0.x + v0.y + v0.z + v0.w + v1.x + v1.y + v1.z + v1.w;
#pragma unroll
    for (int o = 16; o; o >>= 1) s += __shfl_xor_sync(0xffffffffu, s, o);
    if (lane == 0) red[warp] = s;
    __syncthreads();
    float tot = 0.0f;
#pragma unroll
    for (int i = 0; i < 8; i++) tot += red[i];
    float mu = tot * (1.0f / 2048.0f);
    __syncthreads();

    float q =
        (v0.x - mu) * (v0.x - mu) + (v0.y - mu) * (v0.y - mu) +
        (v0.z - mu) * (v0.z - mu) + (v0.w - mu) * (v0.w - mu) +
        (v1.x - mu) * (v1.x - mu) + (v1.y - mu) * (v1.y - mu) +
        (v1.z - mu) * (v1.z - mu) + (v1.w - mu) * (v1.w - mu);
#pragma unroll
    for (int o = 16; o; o >>= 1) q += __shfl_xor_sync(0xffffffffu, q, o);
    if (lane == 0) red[warp] = q;
    __syncthreads();
    float qt = 0.0f;
#pragma unroll
    for (int i = 0; i < 8; i++) qt += red[i];
    float rstd = rsqrtf(qt * (1.0f / 2048.0f) + EPSC);

    float4 w0 = ((const float4*)pw)[tid], w1 = ((const float4*)pw)[tid + 256];
    float4 b0 = ((const float4*)pb)[tid], b1v = ((const float4*)pb)[tid + 256];
    float4 o0, o1;
    o0.x = (v0.x - mu) * rstd * w0.x + b0.x;
    o0.y = (v0.y - mu) * rstd * w0.y + b0.y;
    o0.z = (v0.z - mu) * rstd * w0.z + b0.z;
    o0.w = (v0.w - mu) * rstd * w0.w + b0.w;
    o1.x = (v1.x - mu) * rstd * w1.x + b1v.x;
    o1.y = (v1.y - mu) * rstd * w1.y + b1v.y;
    o1.z = (v1.z - mu) * rstd * w1.z + b1v.z;
    o1.w = (v1.w - mu) * rstd * w1.w + b1v.w;
    float4* dst = (float4*)(g_xq + (size_t)bl * WD);
    dst[tid] = o0;
    dst[tid + 256] = o1;
}

// ---------------- launcher ----------------
extern "C" void kernel_launch(void* const* d_in, const int* in_sizes, int n_in,
                              void* d_out, int out_size)
{
    const float* hs  = (const float*)d_in[0];
    const float* q_w = (const float*)d_in[1];
    const float* v_w = (const float*)d_in[2];
    const float* o_w = (const float*)d_in[3];
    const float* cqw = (const float*)d_in[4];
    const float* cqb = (const float*)d_in[5];
    const float* ckw = (const float*)d_in[6];
    const float* ckb = (const float*)d_in[7];
    const float* lrw = (const float*)d_in[8];
    const float* lrb = (const float*)d_in[9];
    const float* lti = (const float*)d_in[10];
    const float* tnw = (const float*)d_in[11];
    const float* tnb = (const float*)d_in[12];
    const float* W1i = (const float*)d_in[13];
    const float* b1i = (const float*)d_in[14];
    const float* pnw = (const float*)d_in[15];
    const float* pnb = (const float*)d_in[16];
    float* out = (float*)d_out;

    const int M = BZ * LZ;   // 8192
    dim3 gemm_grid(WD / 128, M / 128);

    // xq = hs @ q_w^T  -> g_xq ; XV = hs @ v_w^T -> g_xv
    ttt_sgemm_nt<<<gemm_grid, 256>>>(hs, 0, q_w, nullptr, 1, M, WD, WD);
    ttt_sgemm_nt<<<gemm_grid, 256>>>(hs, 0, v_w, nullptr, 2, M, WD, WD);

    // conv(q,k) + rope -> g_XQ, g_XK
    ttt_conv_rope<<<(ELEMS / 2) / 256, 256>>>(cqw, cqb, ckw, ckb);

    // ttt_lr -> g_lr
    ttt_lr_kernel<<<BZ * LZ, 256>>>(hs, lrw, lrb);

    // scan -> g_scan
    ttt_scan_kernel<<<BZ * NHD, 256>>>(lti, tnw, tnb, W1i, b1i);

    // post-norm -> g_xq (reused)
    ttt_postnorm<<<BZ * LZ, 256>>>(pnw, pnb);

    // out = norm @ o_w^T
    ttt_sgemm_nt<<<gemm_grid, 256>>>(nullptr, 1, o_w, out, 0, M, WD, WD);
}

// round 3
// speedup vs baseline: 1.8607x; 1.8607x over previous
#include <cuda_runtime.h>
#include <cuda_bf16.h>
#include <math.h>
#include <stdint.h>

#define BZ 4
#define LZ 2048
#define WD 2048
#define NHD 32
#define HDM 64
#define MBSZ 16
#define NMBC 128
#define EPSC 1e-6f
#define ELEMS (BZ*LZ*WD)
#define KP 6144            // split-bf16 concatenated K (3*2048)
#define KTILES (KP/64)     // 96

// ---------------- scratch (device globals; no allocation) ----------------
__device__ float g_xq[ELEMS];    // q-projection; later reused as post-norm output
__device__ float g_xv[ELEMS];
__device__ float g_XQ[ELEMS];
__device__ float g_XK[ELEMS];
__device__ float g_scan[ELEMS];
__device__ float g_lr[BZ*NHD*NMBC*MBSZ];
__device__ __nv_bfloat16 g_A_bf[(size_t)8192 * KP];   // [hi | hi | lo]
__device__ __nv_bfloat16 g_B_bf[(size_t)4096 * KP];   // [hi | lo | hi] (q;v or o)

__device__ __forceinline__ float* sel_ptr(int sel) {
    switch (sel) {
        case 1: return g_xq;
        case 2: return g_xv;
        case 5: return g_scan;
    }
    return nullptr;
}

// ---------------- PTX helpers ----------------
__device__ __forceinline__ uint32_t smem_u32(const void* p) {
    uint32_t a;
    asm("{ .reg .u64 t; cvta.to.shared.u64 t, %1; cvt.u32.u64 %0, t; }" : "=r"(a) : "l"(p));
    return a;
}
#define CPA16(d, s) asm volatile("cp.async.cg.shared.global [%0], [%1], 16;" :: "r"(d), "l"(s) : "memory")

__device__ __forceinline__ void ldsm_x4(uint32_t a, uint32_t& r0, uint32_t& r1, uint32_t& r2, uint32_t& r3) {
    asm volatile("ldmatrix.sync.aligned.m8n8.x4.shared.b16 {%0,%1,%2,%3}, [%4];"
                 : "=r"(r0), "=r"(r1), "=r"(r2), "=r"(r3) : "r"(a));
}
__device__ __forceinline__ void mma_bf16(float* c, const uint32_t* a, const uint32_t* b) {
    asm volatile("mma.sync.aligned.m16n8k16.row.col.f32.bf16.bf16.f32 "
                 "{%0,%1,%2,%3}, {%4,%5,%6,%7}, {%8,%9}, {%0,%1,%2,%3};"
                 : "+f"(c[0]), "+f"(c[1]), "+f"(c[2]), "+f"(c[3])
                 : "r"(a[0]), "r"(a[1]), "r"(a[2]), "r"(a[3]), "r"(b[0]), "r"(b[1]));
}

// ---------------- split-bf16 conversion ----------------
// src fp32 [rows,2048] -> dst bf16 [rows,6144]: A: [hi|hi|lo], B: [hi|lo|hi]
__global__ __launch_bounds__(256) void ttt_cvt(const float* __restrict__ ext, int srcsel,
                                               int isA, int rowoff)
{
    const float* src = srcsel ? (const float*)g_xq : ext;
    __nv_bfloat16* dst = isA ? g_A_bf : g_B_bf;
    int t = blockIdx.x * 256 + threadIdx.x;
    float4 v = ((const float4*)src)[t];
    int r = (t >> 9) + rowoff;
    int c4 = t & 511;
    size_t base = (size_t)r * KP + (c4 << 2);

    __nv_bfloat162 h01 = __floats2bfloat162_rn(v.x, v.y);
    __nv_bfloat162 h23 = __floats2bfloat162_rn(v.z, v.w);
    float2 f01 = __bfloat1622float2(h01), f23 = __bfloat1622float2(h23);
    __nv_bfloat162 l01 = __floats2bfloat162_rn(v.x - f01.x, v.y - f01.y);
    __nv_bfloat162 l23 = __floats2bfloat162_rn(v.z - f23.x, v.w - f23.y);
    uint2 hi, lo;
    hi.x = *(uint32_t*)&h01; hi.y = *(uint32_t*)&h23;
    lo.x = *(uint32_t*)&l01; lo.y = *(uint32_t*)&l23;
    *(uint2*)(dst + base)        = hi;
    *(uint2*)(dst + base + 2048) = isA ? hi : lo;
    *(uint2*)(dst + base + 4096) = isA ? lo : hi;
}

// ---------------- bf16 mma.sync GEMM ----------------
// C[m,n] = sum_k A'[m,k]*B'[n,k], K'=6144.
// CTA 128x128 tile, 8 warps (64x32 warp tiles), K-chunk 64, 2-stage cp.async.
// Output columns [0,2048) -> C0, [2048,4096) -> C1 (fused mode).
#define HS_STAGE 32768
__global__ __launch_bounds__(256) void ttt_hgemm(float* Cext, int csel0, int csel1)
{
    extern __shared__ char smem[];
    uint32_t sb = smem_u32(smem);
    const int tid = threadIdx.x;
    const int wid = tid >> 5, lane = tid & 31;
    const int m0 = blockIdx.y << 7;
    const int n0 = blockIdx.x << 7;
    const int mw = (wid >> 2) << 6;       // 0 or 64
    const int nw = (wid & 3) << 5;        // 0,32,64,96

    const __nv_bfloat16* Ab = g_A_bf + (size_t)m0 * KP;
    const __nv_bfloat16* Bb = g_B_bf + (size_t)n0 * KP;

    float acc[4][4][4];
#pragma unroll
    for (int i = 0; i < 4; i++)
#pragma unroll
        for (int j = 0; j < 4; j++)
#pragma unroll
            for (int q = 0; q < 4; q++) acc[i][j][q] = 0.0f;

    auto load_stage = [&](int s, int kt) {
        uint32_t sA = sb + s * HS_STAGE;
        uint32_t sB = sA + 16384;
#pragma unroll
        for (int i = 0; i < 4; i++) {
            int ck = tid + (i << 8);              // 0..1023
            int row = ck >> 3, c = ck & 7;
            uint32_t soff = (uint32_t)(row << 7) + (((uint32_t)(c ^ (row & 7))) << 4);
            CPA16(sA + soff, (const char*)(Ab + (size_t)row * KP + kt * 64 + c * 8));
            CPA16(sB + soff, (const char*)(Bb + (size_t)row * KP + kt * 64 + c * 8));
        }
        asm volatile("cp.async.commit_group;" ::: "memory");
    };

    load_stage(0, 0);
    const int lr15 = lane & 15, lhi = lane >> 4;

    for (int kt = 0; kt < KTILES; kt++) {
        int s = kt & 1;
        if (kt + 1 < KTILES) {
            load_stage(s ^ 1, kt + 1);
            asm volatile("cp.async.wait_group 1;" ::: "memory");
        } else {
            asm volatile("cp.async.wait_group 0;" ::: "memory");
        }
        __syncthreads();

        uint32_t aBase = sb + s * HS_STAGE;
        uint32_t bBase = aBase + 16384;
#pragma unroll
        for (int ks = 0; ks < 4; ks++) {
            uint32_t af[4][4];
#pragma unroll
            for (int mt = 0; mt < 4; mt++) {
                int row = mw + mt * 16 + lr15;
                uint32_t ad = aBase + (row << 7) + ((uint32_t)((2 * ks + lhi) ^ (row & 7)) << 4);
                ldsm_x4(ad, af[mt][0], af[mt][1], af[mt][2], af[mt][3]);
            }
            uint32_t bf[4][2];
#pragma unroll
            for (int np = 0; np < 2; np++) {
                int row = nw + np * 16 + lr15;
                uint32_t bd = bBase + (row << 7) + ((uint32_t)((2 * ks + lhi) ^ (row & 7)) << 4);
                uint32_t r0, r1, r2, r3;
                ldsm_x4(bd, r0, r1, r2, r3);
                bf[np * 2][0] = r0;     bf[np * 2][1] = r2;
                bf[np * 2 + 1][0] = r1; bf[np * 2 + 1][1] = r3;
            }
#pragma unroll
            for (int mt = 0; mt < 4; mt++)
#pragma unroll
                for (int nt = 0; nt < 4; nt++)
                    mma_bf16(acc[mt][nt], af[mt], bf[nt]);
        }
        __syncthreads();
    }

    // epilogue
    float* C0 = csel0 ? sel_ptr(csel0) : Cext;
    float* C1 = csel1 ? sel_ptr(csel1) : nullptr;
#pragma unroll
    for (int mt = 0; mt < 4; mt++) {
#pragma unroll
        for (int nt = 0; nt < 4; nt++) {
            int col = n0 + nw + nt * 8 + (lane & 3) * 2;
            float* C = C0;
            int cc = col;
            if (C1 && col >= 2048) { C = C1; cc = col - 2048; }
            int row = m0 + mw + mt * 16 + (lane >> 2);
            *(float2*)(C + (size_t)row * 2048 + cc) = make_float2(acc[mt][nt][0], acc[mt][nt][1]);
            *(float2*)(C + (size_t)(row + 8) * 2048 + cc) = make_float2(acc[mt][nt][2], acc[mt][nt][3]);
        }
    }
}

// ---------------- causal dwconv (q and k) + interleaved RoPE ----------------
__global__ __launch_bounds__(256) void ttt_conv_rope(
    const float* __restrict__ cqw, const float* __restrict__ cqb,
    const float* __restrict__ ckw, const float* __restrict__ ckb)
{
    int idx = blockIdx.x * 256 + threadIdx.x;
    int pr = idx & (WD / 2 - 1);
    int bl = idx >> 10;
    int l  = bl & (LZ - 1);
    int ch = pr * 2;

    float q0 = cqb[ch], q1 = cqb[ch + 1];
    float k0 = ckb[ch], k1 = ckb[ch + 1];
    const float2* xin = (const float2*)g_xq;
#pragma unroll
    for (int k = 0; k < 4; k++) {
        int ls = l - 3 + k;
        if (ls >= 0) {
            float2 v = xin[(size_t)(bl - 3 + k) * (WD / 2) + pr];
            q0 += v.x * cqw[ch * 4 + k];       q1 += v.y * cqw[(ch + 1) * 4 + k];
            k0 += v.x * ckw[ch * 4 + k];       k1 += v.y * ckw[(ch + 1) * 4 + k];
        }
    }
    int i = (ch & 63) >> 1;
    float fr = (float)(l & 15) * powf(10000.0f, -(float)i * (1.0f / 32.0f));
    float sn, cs;
    sincosf(fr, &sn, &cs);
    float2 oq = make_float2(q0 * cs - q1 * sn, q1 * cs + q0 * sn);
    float2 ok = make_float2(k0 * cs - k1 * sn, k1 * cs + k0 * sn);
    ((float2*)g_XQ)[idx] = oq;
    ((float2*)g_XK)[idx] = ok;
}

// ---------------- ttt_lr ----------------
__global__ __launch_bounds__(256) void ttt_lr_kernel(
    const float* __restrict__ hs, const float* __restrict__ w,
    const float* __restrict__ bias)
{
    __shared__ float row[WD];
    int bl = blockIdx.x, tid = threadIdx.x;
    const float4* src = (const float4*)(hs + (size_t)bl * WD);
    ((float4*)row)[tid]       = src[tid];
    ((float4*)row)[tid + 256] = src[tid + 256];
    __syncthreads();
    int warp = tid >> 5, lane = tid & 31;
    int b = bl >> 11, l = bl & (LZ - 1);
#pragma unroll
    for (int hh = 0; hh < 4; hh++) {
        int h = warp * 4 + hh;
        const float4* wr = (const float4*)(w + (size_t)h * WD);
        const float4* rr = (const float4*)row;
        float s = 0.0f;
#pragma unroll 4
        for (int c = lane; c < WD / 4; c += 32) {
            float4 a = rr[c], bb = wr[c];
            s += a.x * bb.x + a.y * bb.y + a.z * bb.z + a.w * bb.w;
        }
#pragma unroll
        for (int o = 16; o; o >>= 1) s += __shfl_xor_sync(0xffffffffu, s, o);
        if (lane == 0) {
            float sg = 1.0f / (1.0f + expf(-(s + bias[h])));
            g_lr[(((size_t)b * NHD + h) * NMBC + (l >> 4)) * MBSZ + (l & 15)] = sg * (1.0f / 64.0f);
        }
    }
}

// ---------------- the TTT scan: one block per (b,h) ----------------
__global__ __launch_bounds__(256) void ttt_scan_kernel(
    const float* __restrict__ lt_idx,
    const float* __restrict__ lnw_g, const float* __restrict__ lnb_g,
    const float* __restrict__ W1g,   const float* __restrict__ b1g)
{
    __shared__ float W1[64][64];
    __shared__ float sxq[16][68], sxk[16][68], sxv[16][68];
    __shared__ float grad[16][68], z[16][68];
    __shared__ float attn[16][16];
    __shared__ float b1[64], lnw[64], lnb[64], lr[16], tok[16];

    int tid = threadIdx.x;
    int b = blockIdx.x >> 5, h = blockIdx.x & 31;

    for (int o = tid; o < 4096; o += 256)
        ((float*)W1)[o] = W1g[(size_t)h * 4096 + o];
    if (tid < 64) {
        b1[tid]  = b1g[h * 64 + tid];
        lnw[tid] = lnw_g[h * 64 + tid];
        lnb[tid] = lnb_g[h * 64 + tid];
    }
    if (tid < 16) tok[tid] = fmaxf(1.0f / (float)(tid + 1) + lt_idx[tid], 0.0f);
    __syncthreads();

    const int warp = tid >> 5, lane = tid & 31;
    const int ii = tid >> 4;
    const int d0 = (tid & 15) * 4;
    const size_t base = ((size_t)b * LZ) * WD + (size_t)h * HDM;

    for (int n = 0; n < NMBC; n++) {
        {
            size_t g0 = base + (size_t)(n * MBSZ + ii) * WD + d0;
            *(float4*)&sxq[ii][d0] = *(const float4*)&g_XQ[g0];
            *(float4*)&sxk[ii][d0] = *(const float4*)&g_XK[g0];
            *(float4*)&sxv[ii][d0] = *(const float4*)&g_xv[g0];
        }
        if (tid < 16) lr[tid] = g_lr[(((size_t)b * NHD + h) * NMBC + n) * MBSZ + tid];
        __syncthreads();

        {
            float4 acc = *(const float4*)&b1[d0];
#pragma unroll 8
            for (int e = 0; e < 64; e++) {
                float xe = sxk[ii][e];
                float4 w = *(const float4*)&W1[e][d0];
                acc.x += xe * w.x; acc.y += xe * w.y; acc.z += xe * w.z; acc.w += xe * w.w;
            }
            *(float4*)&z[ii][d0] = acc;
        }
        {
            int i = tid >> 4, j = tid & 15;
            float s = 0.0f;
#pragma unroll 8
            for (int d = 0; d < 64; d++) s += sxq[i][d] * sxk[j][d];
            attn[i][j] = s;
        }
        __syncthreads();

        {
#pragma unroll
            for (int rr = 0; rr < 2; rr++) {
                int r = warp * 2 + rr;
                float x0 = z[r][lane], x1 = z[r][lane + 32];
                float s = x0 + x1;
#pragma unroll
                for (int o = 16; o; o >>= 1) s += __shfl_xor_sync(0xffffffffu, s, o);
                float mu = s * (1.0f / 64.0f);
                float e0 = x0 - mu, e1 = x1 - mu;
                float v = e0 * e0 + e1 * e1;
#pragma unroll
                for (int o = 16; o; o >>= 1) v += __shfl_xor_sync(0xffffffffu, v, o);
                float rstd = rsqrtf(v * (1.0f / 64.0f) + EPSC);
                float xh0 = e0 * rstd, xh1 = e1 * rstd;
                float t0 = sxv[r][lane] - sxk[r][lane];
                float t1 = sxv[r][lane + 32] - sxk[r][lane + 32];
                float gy0 = (lnw[lane] * xh0 + lnb[lane] - t0) * lnw[lane];
                float gy1 = (lnw[lane + 32] * xh1 + lnb[lane + 32] - t1) * lnw[lane + 32];
                float s1 = gy0 + gy1, s2 = gy0 * xh0 + gy1 * xh1;
#pragma unroll
                for (int o = 16; o; o >>= 1) {
                    s1 += __shfl_xor_sync(0xffffffffu, s1, o);
                    s2 += __shfl_xor_sync(0xffffffffu, s2, o);
                }
                float sc = rstd * (1.0f / 64.0f);
                grad[r][lane]      = (64.0f * gy0 - s1 - xh0 * s2) * sc;
                grad[r][lane + 32] = (64.0f * gy1 - s1 - xh1 * s2) * sc;
            }
        }
        __syncthreads();

        {
            float4 acc = *(const float4*)&b1[d0];
#pragma unroll 8
            for (int e = 0; e < 64; e++) {
                float xe = sxq[ii][e];
                float4 w = *(const float4*)&W1[e][d0];
                acc.x += xe * w.x; acc.y += xe * w.y; acc.z += xe * w.z; acc.w += xe * w.w;
            }
            float tk = tok[ii];
            for (int j = 0; j <= ii; j++) {
                float cf = tk * lr[j] * (attn[ii][j] + 1.0f);
                float4 gr = *(const float4*)&grad[j][d0];
                acc.x -= cf * gr.x; acc.y -= cf * gr.y; acc.z -= cf * gr.z; acc.w -= cf * gr.w;
            }
            *(float4*)&z[ii][d0] = acc;
        }
        __syncthreads();

        {
#pragma unroll
            for (int rr = 0; rr < 2; rr++) {
                int r = warp * 2 + rr;
                float x0 = z[r][lane], x1 = z[r][lane + 32];
                float s = x0 + x1;
#pragma unroll
                for (int o = 16; o; o >>= 1) s += __shfl_xor_sync(0xffffffffu, s, o);
                float mu = s * (1.0f / 64.0f);
                float e0 = x0 - mu, e1 = x1 - mu;
                float v = e0 * e0 + e1 * e1;
#pragma unroll
                for (int o = 16; o; o >>= 1) v += __shfl_xor_sync(0xffffffffu, v, o);
                float rstd = rsqrtf(v * (1.0f / 64.0f) + EPSC);
                size_t go = base + (size_t)(n * MBSZ + r) * WD;
                g_scan[go + lane]      = sxq[r][lane]      + lnw[lane] * (e0 * rstd)      + lnb[lane];
                g_scan[go + lane + 32] = sxq[r][lane + 32] + lnw[lane + 32] * (e1 * rstd) + lnb[lane + 32];
            }
        }

        {
            float te = tok[15];
#pragma unroll
            for (int p = 0; p < 4; p++) {
                int d = ii * 4 + p;
                float4 acc = *(const float4*)&W1[d][d0];
#pragma unroll
                for (int j = 0; j < 16; j++) {
                    float cf = te * lr[j] * sxk[j][d];
                    float4 gr = *(const float4*)&grad[j][d0];
                    acc.x -= cf * gr.x; acc.y -= cf * gr.y; acc.z -= cf * gr.z; acc.w -= cf * gr.w;
                }
                *(float4*)&W1[d][d0] = acc;
            }
            if (tid < 64) {
                float s = 0.0f;
#pragma unroll
                for (int j = 0; j < 16; j++) s += lr[j] * grad[j][tid];
                b1[tid] -= te * s;
            }
        }
        __syncthreads();
    }
}

// ---------------- post layer-norm ----------------
__global__ __launch_bounds__(256) void ttt_postnorm(
    const float* __restrict__ pw, const float* __restrict__ pb)
{
    __shared__ float red[8];
    int bl = blockIdx.x, tid = threadIdx.x;
    int lane = tid & 31, warp = tid >> 5;
    const float4* src = (const float4*)(g_scan + (size_t)bl * WD);
    float4 v0 = src[tid], v1 = src[tid + 256];

    float s = v0.x + v0.y + v0.z + v0.w + v1.x + v1.y + v1.z + v1.w;
#pragma unroll
    for (int o = 16; o; o >>= 1) s += __shfl_xor_sync(0xffffffffu, s, o);
    if (lane == 0) red[warp] = s;
    __syncthreads();
    float tot = 0.0f;
#pragma unroll
    for (int i = 0; i < 8; i++) tot += red[i];
    float mu = tot * (1.0f / 2048.0f);
    __syncthreads();

    float q =
        (v0.x - mu) * (v0.x - mu) + (v0.y - mu) * (v0.y - mu) +
        (v0.z - mu) * (v0.z - mu) + (v0.w - mu) * (v0.w - mu) +
        (v1.x - mu) * (v1.x - mu) + (v1.y - mu) * (v1.y - mu) +
        (v1.z - mu) * (v1.z - mu) + (v1.w - mu) * (v1.w - mu);
#pragma unroll
    for (int o = 16; o; o >>= 1) q += __shfl_xor_sync(0xffffffffu, q, o);
    if (lane == 0) red[warp] = q;
    __syncthreads();
    float qt = 0.0f;
#pragma unroll
    for (int i = 0; i < 8; i++) qt += red[i];
    float rstd = rsqrtf(qt * (1.0f / 2048.0f) + EPSC);

    float4 w0 = ((const float4*)pw)[tid], w1 = ((const float4*)pw)[tid + 256];
    float4 b0 = ((const float4*)pb)[tid], b1v = ((const float4*)pb)[tid + 256];
    float4 o0, o1;
    o0.x = (v0.x - mu) * rstd * w0.x + b0.x;
    o0.y = (v0.y - mu) * rstd * w0.y + b0.y;
    o0.z = (v0.z - mu) * rstd * w0.z + b0.z;
    o0.w = (v0.w - mu) * rstd * w0.w + b0.w;
    o1.x = (v1.x - mu) * rstd * w1.x + b1v.x;
    o1.y = (v1.y - mu) * rstd * w1.y + b1v.y;
    o1.z = (v1.z - mu) * rstd * w1.z + b1v.z;
    o1.w = (v1.w - mu) * rstd * w1.w + b1v.w;
    float4* dst = (float4*)(g_xq + (size_t)bl * WD);
    dst[tid] = o0;
    dst[tid + 256] = o1;
}

// ---------------- launcher ----------------
extern "C" void kernel_launch(void* const* d_in, const int* in_sizes, int n_in,
                              void* d_out, int out_size)
{
    const float* hs  = (const float*)d_in[0];
    const float* q_w = (const float*)d_in[1];
    const float* v_w = (const float*)d_in[2];
    const float* o_w = (const float*)d_in[3];
    const float* cqw = (const float*)d_in[4];
    const float* cqb = (const float*)d_in[5];
    const float* ckw = (const float*)d_in[6];
    const float* ckb = (const float*)d_in[7];
    const float* lrw = (const float*)d_in[8];
    const float* lrb = (const float*)d_in[9];
    const float* lti = (const float*)d_in[10];
    const float* tnw = (const float*)d_in[11];
    const float* tnb = (const float*)d_in[12];
    const float* W1i = (const float*)d_in[13];
    const float* b1i = (const float*)d_in[14];
    const float* pnw = (const float*)d_in[15];
    const float* pnb = (const float*)d_in[16];
    float* out = (float*)d_out;

    static int smem_set = 0;
    if (!smem_set) {
        cudaFuncSetAttribute(ttt_hgemm, cudaFuncAttributeMaxDynamicSharedMemorySize, 2 * HS_STAGE);
        smem_set = 1;
    }

    // fused QV projection: A=hs, B=[q_w; v_w]
    ttt_cvt<<<16384, 256>>>(hs, 0, 1, 0);
    ttt_cvt<<<4096, 256>>>(q_w, 0, 0, 0);
    ttt_cvt<<<4096, 256>>>(v_w, 0, 0, 2048);
    ttt_hgemm<<<dim3(32, 64), 256, 2 * HS_STAGE>>>(nullptr, 1, 2);   // -> g_xq, g_xv

    ttt_conv_rope<<<(ELEMS / 2) / 256, 256>>>(cqw, cqb, ckw, ckb);
    ttt_lr_kernel<<<BZ * LZ, 256>>>(hs, lrw, lrb);
    ttt_scan_kernel<<<BZ * NHD, 256>>>(lti, tnw, tnb, W1i, b1i);
    ttt_postnorm<<<BZ * LZ, 256>>>(pnw, pnb);   // -> g_xq

    // final GEMM: A=postnorm(g_xq), B=o_w
    ttt_cvt<<<16384, 256>>>(nullptr, 1, 1, 0);
    ttt_cvt<<<4096, 256>>>(o_w, 0, 0, 0);
    ttt_hgemm<<<dim3(16, 64), 256, 2 * HS_STAGE>>>(out, 0, 0);
}